// round 5
// baseline (speedup 1.0000x reference)
#include <cuda_runtime.h>
#include <math.h>

// Problem constants
#define SEQ   256
#define BAT   64
#define EMB   300
#define HID2  256          // H2
#define NJ    2048         // 4*H2 * 2 directions
#define NTAG  10
#define NROWS 16384        // SEQ*BAT
#define NCTA_REC 128       // persistent recurrent CTAs (64 per direction)

// ---------------- device scratch (static allocation only) ----------------
__device__ float    g_WT[EMB * NJ];                        // wih transposed, [e][j]
__device__ float    g_P[(size_t)NROWS * NJ];               // input projections + biases
__device__ float    g_hbuf[2 * 2 * BAT * HID2];            // [parity][dir][b][k]
__device__ float    g_Hout[2 * (size_t)NROWS * HID2];      // [dir][s*B+b][k]
__device__ float    g_F[NROWS * NTAG + 64];                // feats (B,S,T) flat, padded
__device__ unsigned g_ctr;                                 // grid barrier counter

// ---------------- kernel 0a: transpose wih into [e][j] ----------------
__global__ void transpose_wih(const float* __restrict__ wf, const float* __restrict__ wb) {
    int idx = blockIdx.x * 256 + threadIdx.x;
    if (idx >= EMB * NJ) return;
    int e = idx / NJ, j = idx % NJ;
    g_WT[idx] = (j < 1024) ? wf[j * EMB + e] : wb[(j - 1024) * EMB + e];
}

// ---------------- kernel 0b: init barrier + copy h0 into hbuf[0] ----------------
__global__ void init_state(const float* __restrict__ h0) {
    int idx = blockIdx.x * 256 + threadIdx.x;
    if (idx == 0) g_ctr = 0u;
    if (idx < 2 * BAT * HID2) g_hbuf[idx] = h0[idx];  // h0 is (2,B,H2) = same layout
}

// ---------------- kernel 1: fused gather + input GEMM ----------------
// P[r][j] = sum_e emb[sent[r]][e] * WT[e][j] + bih[j] + bhh[j]
// M=16384, N=2048, K=300. 64x64 tile, 4x4 per thread, BK=20 (300 = 15*20).
__global__ void __launch_bounds__(256) gemm_input(
    const int* __restrict__ sent, const float* __restrict__ emb,
    const float* __restrict__ bih_f, const float* __restrict__ bhh_f,
    const float* __restrict__ bih_b, const float* __restrict__ bhh_b) {

    __shared__ float As[20][68];   // [k][i], padded stride 68 (16B-aligned rows)
    __shared__ float Bs[20][64];   // [k][j]
    __shared__ int   toks[64];

    int bx = blockIdx.x & 31;      // N tile (32)
    int by = blockIdx.x >> 5;      // M tile (256)
    int tid = threadIdx.x;
    int row0 = by * 64, col0 = bx * 64;

    if (tid < 64) toks[tid] = sent[row0 + tid];
    __syncthreads();

    int ty = tid >> 4, tx = tid & 15;         // 16x16 thread grid
    int li = tid >> 2;                        // A-load row
    int le = (tid & 3) * 5;                   // A-load e base

    float4 acc[4];
    #pragma unroll
    for (int i = 0; i < 4; i++) acc[i] = make_float4(0.f, 0.f, 0.f, 0.f);

    long tokoff = (long)toks[li] * EMB;

    for (int kc = 0; kc < 15; kc++) {
        int e0 = kc * 20;
        const float* ebase = emb + tokoff + e0 + le;
        #pragma unroll
        for (int q = 0; q < 5; q++) As[le + q][li] = ebase[q];
        #pragma unroll
        for (int u = 0; u < 5; u++) {
            int idx = tid + u * 256;
            int kk = idx >> 6, j = idx & 63;
            Bs[kk][j] = g_WT[(size_t)(e0 + kk) * NJ + col0 + j];
        }
        __syncthreads();
        #pragma unroll
        for (int kk = 0; kk < 20; kk++) {
            float4 b4 = *(const float4*)&Bs[kk][tx * 4];
            float4 a4 = *(const float4*)&As[kk][ty * 4];
            acc[0].x += a4.x * b4.x; acc[0].y += a4.x * b4.y; acc[0].z += a4.x * b4.z; acc[0].w += a4.x * b4.w;
            acc[1].x += a4.y * b4.x; acc[1].y += a4.y * b4.y; acc[1].z += a4.y * b4.z; acc[1].w += a4.y * b4.w;
            acc[2].x += a4.z * b4.x; acc[2].y += a4.z * b4.y; acc[2].z += a4.z * b4.z; acc[2].w += a4.z * b4.w;
            acc[3].x += a4.w * b4.x; acc[3].y += a4.w * b4.y; acc[3].z += a4.w * b4.z; acc[3].w += a4.w * b4.w;
        }
        __syncthreads();
    }

    int jg = col0 + tx * 4;
    float bias[4];
    #pragma unroll
    for (int jj = 0; jj < 4; jj++) {
        int j = jg + jj;
        bias[jj] = (j < 1024) ? (bih_f[j] + bhh_f[j]) : (bih_b[j - 1024] + bhh_b[j - 1024]);
    }
    #pragma unroll
    for (int ii = 0; ii < 4; ii++) {
        float4 v = acc[ii];
        v.x += bias[0]; v.y += bias[1]; v.z += bias[2]; v.w += bias[3];
        *(float4*)&g_P[(size_t)(row0 + ty * 4 + ii) * NJ + jg] = v;
    }
}

// ---------------- kernel 2: persistent bidirectional LSTM recurrence ----------------
// 128 CTAs: dir = bx>>6, each CTA owns 4 hidden units (16 gate rows of Whh in SMEM).
// Per step: broadcast-load h (64KB) into SMEM, 64x16 gate dot-products, gate staging,
// cell update, write h to double-buffered global + history, grid spin barrier.
__global__ void __launch_bounds__(256, 1) lstm_recurrent(
    const float* __restrict__ whh_f, const float* __restrict__ whh_b,
    const float* __restrict__ c0) {

    extern __shared__ float sm[];
    float* w_s    = sm;                       // 16 * 268
    float* h_s    = sm + 16 * 268;            // 64 * 256
    float* gate_s = h_s + 64 * 256;           // 16 * 65 (padded)
    float* c_s    = gate_s + 16 * 65;         // 256

    int tid = threadIdx.x;
    int dir = blockIdx.x >> 6;
    int k0  = (blockIdx.x & 63) * 4;
    const float* whh = dir ? whh_b : whh_f;

    // load Whh slice (16 rows x 256) once, float4
    for (int idx = tid; idx < 16 * 64; idx += 256) {
        int jl = idx >> 6, kq = idx & 63;
        int jgl = (jl >> 2) * 256 + k0 + (jl & 3);
        float4 v = *(const float4*)&whh[(size_t)jgl * 256 + kq * 4];
        *(float4*)&w_s[jl * 268 + kq * 4] = v;
    }
    // load cell state slice (persists in SMEM for all 256 steps)
    {
        int b = tid >> 2, kl = tid & 3;
        c_s[tid] = c0[(dir * 64 + b) * 256 + k0 + kl];
    }
    __syncthreads();

    const int jl = tid & 15, bi = tid >> 4;      // dot-product mapping
    const int jg = (jl >> 2) * 256 + k0 + (jl & 3);
    const int bb = tid >> 2, kk2 = tid & 3;      // cell-update mapping

    for (int step = 0; step < 256; step++) {
        int p = step & 1;
        int sidx = dir ? (255 - step) : step;

        // broadcast-load h (bypass L1: cross-SM producer/consumer)
        {
            const float4* src = (const float4*)(g_hbuf + (p * 2 + dir) * (BAT * HID2));
            float4* dst = (float4*)h_s;
            #pragma unroll
            for (int u = 0; u < 16; u++) dst[tid + u * 256] = __ldcg(src + tid + u * 256);
        }
        __syncthreads();

        // 4 dot products (same gate row, batches bi, bi+16, bi+32, bi+48)
        const float4* wrow = (const float4*)(w_s + jl * 268);
        const float4* h0r = (const float4*)(h_s + (bi)      * 256);
        const float4* h1r = (const float4*)(h_s + (bi + 16) * 256);
        const float4* h2r = (const float4*)(h_s + (bi + 32) * 256);
        const float4* h3r = (const float4*)(h_s + (bi + 48) * 256);
        float4 a0 = make_float4(0,0,0,0), a1 = a0, a2 = a0, a3 = a0;
        #pragma unroll 8
        for (int q = 0; q < 64; q++) {
            float4 w = wrow[q];
            float4 x;
            x = h0r[q]; a0.x += w.x*x.x; a0.y += w.y*x.y; a0.z += w.z*x.z; a0.w += w.w*x.w;
            x = h1r[q]; a1.x += w.x*x.x; a1.y += w.y*x.y; a1.z += w.z*x.z; a1.w += w.w*x.w;
            x = h2r[q]; a2.x += w.x*x.x; a2.y += w.y*x.y; a2.z += w.z*x.z; a2.w += w.w*x.w;
            x = h3r[q]; a3.x += w.x*x.x; a3.y += w.y*x.y; a3.z += w.z*x.z; a3.w += w.w*x.w;
        }
        const float* Pb = g_P + (size_t)(sidx * 64) * NJ + dir * 1024 + jg;
        gate_s[jl * 65 + bi]      = (a0.x + a0.y) + (a0.z + a0.w) + Pb[(size_t)(bi)      * NJ];
        gate_s[jl * 65 + bi + 16] = (a1.x + a1.y) + (a1.z + a1.w) + Pb[(size_t)(bi + 16) * NJ];
        gate_s[jl * 65 + bi + 32] = (a2.x + a2.y) + (a2.z + a2.w) + Pb[(size_t)(bi + 32) * NJ];
        gate_s[jl * 65 + bi + 48] = (a3.x + a3.y) + (a3.z + a3.w) + Pb[(size_t)(bi + 48) * NJ];
        __syncthreads();

        // cell/hidden update: gate order i,f,g,o
        {
            float gi = gate_s[(0  + kk2) * 65 + bb];
            float gf = gate_s[(4  + kk2) * 65 + bb];
            float gg = gate_s[(8  + kk2) * 65 + bb];
            float go = gate_s[(12 + kk2) * 65 + bb];
            float si = 1.f / (1.f + expf(-gi));
            float sf = 1.f / (1.f + expf(-gf));
            float so = 1.f / (1.f + expf(-go));
            float c = sf * c_s[tid] + si * tanhf(gg);
            c_s[tid] = c;
            float h = so * tanhf(c);
            __stcg(&g_hbuf[((p ^ 1) * 2 + dir) * (BAT * HID2) + bb * 256 + k0 + kk2], h);
            g_Hout[(size_t)dir * ((size_t)NROWS * HID2) + (size_t)(sidx * 64 + bb) * 256 + k0 + kk2] = h;
        }

        // grid-wide barrier (all 128 CTAs co-resident: 128 <= 148 SMs, 1 CTA/SM fits)
        __threadfence();
        __syncthreads();
        if (tid == 0) {
            atomicAdd(&g_ctr, 1u);
            unsigned target = (unsigned)NCTA_REC * (unsigned)(step + 1);
            while (*((volatile unsigned*)&g_ctr) < target) { }
        }
        __syncthreads();
    }
}

// ---------------- kernel 3: output features F[r][t] ----------------
__global__ void __launch_bounds__(256) feats_kernel(
    const float* __restrict__ Wout, const float* __restrict__ bout) {
    int warp = threadIdx.x >> 5;
    int lane = threadIdx.x & 31;
    int r = blockIdx.x * 8 + warp;
    const float* hf = g_Hout + (size_t)r * 256;
    const float* hb = g_Hout + (size_t)NROWS * HID2 + (size_t)r * 256;
    float a[8], c[8];
    #pragma unroll
    for (int q = 0; q < 8; q++) { a[q] = hf[lane * 8 + q]; c[q] = hb[lane * 8 + q]; }
    #pragma unroll
    for (int t = 0; t < NTAG; t++) {
        const float* w = Wout + t * 512 + lane * 8;
        float s = 0.f;
        #pragma unroll
        for (int q = 0; q < 8; q++) s += a[q] * w[q] + c[q] * w[256 + q];
        #pragma unroll
        for (int off = 16; off; off >>= 1) s += __shfl_xor_sync(0xffffffffu, s, off);
        if (lane == 0) g_F[r * NTAG + t] = s + bout[t];
    }
}

// ---------------- kernel 4: Viterbi decode (one warp per batch) ----------------
__global__ void viterbi_kernel(const float* __restrict__ trans, float* __restrict__ out) {
    int b = blockIdx.x;
    int lane = threadIdx.x;
    __shared__ unsigned char bps[256][16];

    float tr[NTAG];
    if (lane < NTAG) {
        #pragma unroll
        for (int p = 0; p < NTAG; p++) tr[p] = trans[lane * NTAG + p];
    } else {
        #pragma unroll
        for (int p = 0; p < NTAG; p++) tr[p] = -10000.0f;
    }
    float fv = (lane == 8) ? 0.f : -10000.0f;   // START_IDX = 8
    const float* fb = g_F + b * (SEQ * NTAG);

    for (int s = 0; s < SEQ; s++) {
        float m = -3.4e38f; int arg = 0;
        #pragma unroll
        for (int p = 0; p < NTAG; p++) {
            float v = __shfl_sync(0xffffffffu, fv, p) + tr[p];
            if (v > m) { m = v; arg = p; }      // strict >: first-max wins (jnp.argmax)
        }
        float feat = 0.f;
        if (lane < NTAG) feat = fb[s * NTAG + lane];
        fv = m + feat;
        if (lane < NTAG) bps[s][lane] = (unsigned char)arg;
    }

    float term = fv;
    if (lane < NTAG) term += trans[9 * NTAG + lane];   // STOP_IDX row = 9
    float best = -3.4e38f; int bt = 0;
    #pragma unroll
    for (int t = 0; t < NTAG; t++) {
        float v = __shfl_sync(0xffffffffu, term, t);
        if (v > best) { best = v; bt = t; }
    }
    __syncwarp();
    if (lane == 0) {
        out[b] = best;                                   // path_score (B,1)
        int cur = bt;
        out[64 + b * SEQ + (SEQ - 1)] = (float)cur;      // path (B,S)
        for (int s = SEQ - 2; s >= 0; s--) {
            cur = bps[s + 1][cur];
            out[64 + b * SEQ + s] = (float)cur;
        }
    }
}

// ---------------- launch ----------------
extern "C" void kernel_launch(void* const* d_in, const int* in_sizes, int n_in,
                              void* d_out, int out_size) {
    const int*   sent  = (const int*)d_in[0];
    const float* emb   = (const float*)d_in[1];
    const float* wih_f = (const float*)d_in[2];
    const float* whh_f = (const float*)d_in[3];
    const float* bih_f = (const float*)d_in[4];
    const float* bhh_f = (const float*)d_in[5];
    const float* wih_b = (const float*)d_in[6];
    const float* whh_b = (const float*)d_in[7];
    const float* bih_b = (const float*)d_in[8];
    const float* bhh_b = (const float*)d_in[9];
    const float* Wout  = (const float*)d_in[10];
    const float* bout  = (const float*)d_in[11];

    // Dict order has transitions last; signature order has it at index 12.
    const float *trans, *h0, *c0;
    if (n_in > 14 && in_sizes[12] == 100) {
        trans = (const float*)d_in[12]; h0 = (const float*)d_in[13]; c0 = (const float*)d_in[14];
    } else {
        h0 = (const float*)d_in[12]; c0 = (const float*)d_in[13]; trans = (const float*)d_in[14];
    }
    float* out = (float*)d_out;

    transpose_wih<<<(EMB * NJ + 255) / 256, 256>>>(wih_f, wih_b);
    init_state<<<128, 256>>>(h0);
    gemm_input<<<8192, 256>>>(sent, emb, bih_f, bhh_f, bih_b, bhh_b);

    const int smem_rec = (16 * 268 + 64 * 256 + 16 * 65 + 256) * (int)sizeof(float); // 87872 B
    cudaFuncSetAttribute(lstm_recurrent, cudaFuncAttributeMaxDynamicSharedMemorySize, smem_rec);
    lstm_recurrent<<<NCTA_REC, 256, smem_rec>>>(whh_f, whh_b, c0);

    feats_kernel<<<NROWS / 8, 256>>>(Wout, bout);
    viterbi_kernel<<<BAT, 32>>>(trans, out);
}